// round 11
// baseline (speedup 1.0000x reference)
#include <cuda_runtime.h>
#include <cuda_fp16.h>
#include <math.h>
#include <stdint.h>

#define NHEAD 16
#define DK 64
#define DMODEL 1024
#define BATCH 4
#define SEQ 2048
#define MTOT (BATCH*SEQ)                  // 8192
#define ACTN ((size_t)MTOT*DMODEL)
#define WN   ((size_t)DMODEL*DMODEL)
#define HS   ((size_t)BATCH*NHEAD*SEQ*DK)

// inputs single-rounded fp16 (3 slots: q,k,v); x (attn out) split hi/lo
__device__ __half g_a [3*ACTN];
__device__ __half g_xh[ACTN];
__device__ __half g_xl[ACTN];
__device__ __half g_w [4*WN];
__device__ __half g_qh[HS], g_ql[HS];     // Q split (scaled by 1/8)
__device__ __half g_k [HS];               // K single-rounded
__device__ __half g_v [HS];               // V single-rounded

// ---------------- helpers ----------------
__device__ __forceinline__ uint32_t smem_u32(const void* p) {
    uint32_t a;
    asm("{ .reg .u64 t; cvta.to.shared.u64 t, %1; cvt.u32.u64 %0, t; }" : "=r"(a) : "l"(p));
    return a;
}
__device__ __forceinline__ void cp_async16(uint32_t dst, const void* src) {
    asm volatile("cp.async.cg.shared.global [%0], [%1], 16;" :: "r"(dst), "l"(src));
}
#define CP_COMMIT() asm volatile("cp.async.commit_group;" ::: "memory")
#define CP_WAIT(n)  asm volatile("cp.async.wait_group %0;" :: "n"(n) : "memory")

__device__ __forceinline__ void ldsm4(uint32_t a, uint32_t* r) {
    asm volatile("ldmatrix.sync.aligned.m8n8.x4.shared.b16 {%0,%1,%2,%3}, [%4];"
        : "=r"(r[0]), "=r"(r[1]), "=r"(r[2]), "=r"(r[3]) : "r"(a));
}
__device__ __forceinline__ void ldsm4t(uint32_t a, uint32_t* r) {
    asm volatile("ldmatrix.sync.aligned.m8n8.x4.trans.shared.b16 {%0,%1,%2,%3}, [%4];"
        : "=r"(r[0]), "=r"(r[1]), "=r"(r[2]), "=r"(r[3]) : "r"(a));
}
__device__ __forceinline__ void mma_f16(float* c, const uint32_t* a, const uint32_t* b) {
    asm volatile("mma.sync.aligned.m16n8k16.row.col.f32.f16.f16.f32 "
        "{%0,%1,%2,%3}, {%4,%5,%6,%7}, {%8,%9}, {%0,%1,%2,%3};"
        : "+f"(c[0]), "+f"(c[1]), "+f"(c[2]), "+f"(c[3])
        : "r"(a[0]), "r"(a[1]), "r"(a[2]), "r"(a[3]), "r"(b[0]), "r"(b[1]));
}
__device__ __forceinline__ uint32_t pack_h(float p0, float p1) {
    __half2 hv = __floats2half2_rn(p0, p1);
    return *(uint32_t*)&hv;
}
__device__ __forceinline__ void pack_hl(float p0, float p1, uint32_t& h, uint32_t& l) {
    __half2 hv = __floats2half2_rn(p0, p1);
    __half2 lv = __floats2half2_rn(p0 - __low2float(hv), p1 - __high2float(hv));
    h = *(uint32_t*)&hv;
    l = *(uint32_t*)&lv;
}

// ---------------------------------------------------------------------------
// fp32 -> fp16 converts (single round)
// ---------------------------------------------------------------------------
__global__ void cvt_act_kernel(const float* __restrict__ q, const float* __restrict__ k,
                               const float* __restrict__ v, int n4)
{
    int z = blockIdx.y;
    const float* src = (z == 0) ? q : (z == 1) ? k : v;
    __half* dst = g_a + (size_t)z * ACTN;
    int i = blockIdx.x * blockDim.x + threadIdx.x;
    if (i >= n4) return;
    float4 vv = ((const float4*)src)[i];
    ((uint32_t*)dst)[2*i]   = pack_h(vv.x, vv.y);
    ((uint32_t*)dst)[2*i+1] = pack_h(vv.z, vv.w);
}

__global__ void cvt_w_kernel(const float* __restrict__ w0, const float* __restrict__ w1,
                             const float* __restrict__ w2, const float* __restrict__ w3,
                             int n4)
{
    int z = blockIdx.y;
    const float* src = (z == 0) ? w0 : (z == 1) ? w1 : (z == 2) ? w2 : w3;
    __half* hi = g_w + (size_t)z * WN;
    int i = blockIdx.x * blockDim.x + threadIdx.x;
    if (i >= n4) return;
    float4 vv = ((const float4*)src)[i];
    ((uint32_t*)hi)[2*i]   = pack_h(vv.x, vv.y);
    ((uint32_t*)hi)[2*i+1] = pack_h(vv.z, vv.w);
}

// ---------------------------------------------------------------------------
// GEMM template. MODE 0: QKV, 1-term (A single x W single), 4-stage pipeline.
//                MODE 1: final, 2-term ((Xh+Xl) x W), 3-stage pipeline.
// CTA 128x128, K-chunk 32, 2 CTAs/SM. 8 warps 4(M)x2(N), warp 32x64.
// ---------------------------------------------------------------------------
#define GKC 32
#define GSTRIDE 80
#define GA_BUF (128*GSTRIDE)             // 10240
#define GSTAGE0 (2*GA_BUF)               // A, W        = 20480
#define GSTAGE1 (3*GA_BUF)               // Xh, Xl, W   = 30720
#define GEMM_SMEM0 (4*GSTAGE0)           // 81920
#define GEMM_SMEM1 (3*GSTAGE1)           // 92160

template<int MODE>
__device__ __forceinline__ void g_load_stage(uint32_t base,
                                             const __half* A0, const __half* A1,
                                             const __half* W_g,
                                             int bm, int bn, int k0, int tid)
{
    constexpr int NCH = (MODE == 0) ? 4 : 6;
#pragma unroll
    for (int j = 0; j < NCH; j++) {
        int g = tid + 256 * j;
        int buf, cid;
        if (MODE == 0) { buf = g >> 9; cid = g & 511; }        // 0:A 1:W
        else           { buf = g >> 9; cid = g & 511; }        // 0:Xh 1:Xl 2:W
        int row = cid >> 2;
        int ch  = cid & 3;
        const __half* src;
        int rbase;
        if (MODE == 0) {
            src = buf ? W_g : A0;
            rbase = buf ? bn : bm;
        } else {
            src = (buf == 0) ? A0 : (buf == 1) ? A1 : W_g;
            rbase = (buf < 2) ? bm : bn;
        }
        cp_async16(base + buf * GA_BUF + row * GSTRIDE + ch * 16,
                   src + (size_t)(rbase + row) * DMODEL + k0 + ch * 8);
    }
}

template<int MODE>
__global__ __launch_bounds__(256, 2)
void gemm_mma_kernel(const float* __restrict__ b0, const float* __restrict__ b1,
                     const float* __restrict__ b2, float* __restrict__ Cout)
{
    extern __shared__ __align__(128) char smg[];
    const uint32_t sb = smem_u32(smg);
    const int tid = threadIdx.x;
    const int lane = tid & 31;
    const int wid = tid >> 5;
    const int wr = (wid >> 1) * 32;
    const int wn = (wid & 1) * 64;
    const int bm = blockIdx.y * 128;
    const int bn = blockIdx.x * 128;
    const int z = blockIdx.z;

    constexpr int NSTG  = (MODE == 0) ? 4 : 3;
    constexpr int STAGE = (MODE == 0) ? GSTAGE0 : GSTAGE1;
    constexpr int WOFF  = (MODE == 0) ? GA_BUF : 2 * GA_BUF;

    const __half* A0 = (MODE == 0) ? g_a + (size_t)z * ACTN : g_xh;
    const __half* A1 = (MODE == 0) ? (const __half*)nullptr : g_xl;
    const __half* W_g = g_w + (size_t)((MODE == 0) ? z : 3) * WN;
    const float* bias = (MODE == 1) ? b0 : (z == 0) ? b0 : (z == 1) ? b1 : b2;

    float acc[2][8][4];
#pragma unroll
    for (int a = 0; a < 2; a++)
#pragma unroll
        for (int b = 0; b < 8; b++)
#pragma unroll
            for (int c = 0; c < 4; c++) acc[a][b][c] = 0.f;

    g_load_stage<MODE>(sb + 0 * STAGE, A0, A1, W_g, bm, bn, 0, tid);       CP_COMMIT();
    g_load_stage<MODE>(sb + 1 * STAGE, A0, A1, W_g, bm, bn, GKC, tid);     CP_COMMIT();
    if (MODE == 0) {
        g_load_stage<MODE>(sb + 2 * STAGE, A0, A1, W_g, bm, bn, 2 * GKC, tid);
        CP_COMMIT();
    }

    const int NIT = DMODEL / GKC;   // 32
    const uint32_t a_row = (lane & 15);
    const uint32_t a_k8  = (lane >> 4) << 3;
    const uint32_t b_row = ((lane >> 4) << 3) + (lane & 7);
    const uint32_t b_k8  = ((lane >> 3) & 1) << 3;

    for (int it = 0; it < NIT; it++) {
        int rem = NIT - 1 - it;
        if (MODE == 0) {
            if      (rem >= 2) { CP_WAIT(2); }
            else if (rem == 1) { CP_WAIT(1); }
            else               { CP_WAIT(0); }
        } else {
            if (rem >= 1) { CP_WAIT(1); } else { CP_WAIT(0); }
        }
        __syncthreads();

        const int pf = (MODE == 0) ? 3 : 2;
        if (it + pf < NIT) {
            g_load_stage<MODE>(sb + ((it + pf) % NSTG) * STAGE, A0, A1, W_g,
                               bm, bn, (it + pf) * GKC, tid);
            CP_COMMIT();
        }

        uint32_t base = sb + (it % NSTG) * STAGE;
#pragma unroll
        for (int ks = 0; ks < 2; ks++) {
            const int k0 = ks * 16;
            uint32_t Ah[2][4], Al[2][4], Bf[4][4];
#pragma unroll
            for (int mf = 0; mf < 2; mf++) {
                uint32_t ra = base + (wr + mf * 16 + a_row) * GSTRIDE + (k0 + a_k8) * 2;
                ldsm4(ra, Ah[mf]);
                if (MODE == 1) ldsm4(ra + GA_BUF, Al[mf]);
            }
#pragma unroll
            for (int np = 0; np < 4; np++) {
                uint32_t rb = base + WOFF + (wn + np * 16 + b_row) * GSTRIDE
                              + (k0 + b_k8) * 2;
                ldsm4(rb, Bf[np]);
            }
#pragma unroll
            for (int np = 0; np < 4; np++)
#pragma unroll
                for (int nn = 0; nn < 2; nn++)
#pragma unroll
                    for (int mf = 0; mf < 2; mf++)
                        mma_f16(acc[mf][np * 2 + nn], Ah[mf], Bf[np] + 2 * nn);
            if (MODE == 1) {
#pragma unroll
                for (int np = 0; np < 4; np++)
#pragma unroll
                    for (int nn = 0; nn < 2; nn++)
#pragma unroll
                        for (int mf = 0; mf < 2; mf++)
                            mma_f16(acc[mf][np * 2 + nn], Al[mf], Bf[np] + 2 * nn);
            }
        }
    }

    // epilogue
    const float sc = (MODE == 0 && z == 0) ? 0.125f : 1.0f;
#pragma unroll
    for (int mf = 0; mf < 2; mf++) {
#pragma unroll
        for (int nf = 0; nf < 8; nf++) {
            int r0 = bm + wr + mf * 16 + (lane >> 2);
            int c0 = bn + wn + nf * 8 + (lane & 3) * 2;
            float bs0 = bias[c0], bs1 = bias[c0 + 1];
#pragma unroll
            for (int hh = 0; hh < 2; hh++) {
                int row = r0 + 8 * hh;
                float v0 = (acc[mf][nf][2 * hh + 0] + bs0) * sc;
                float v1 = (acc[mf][nf][2 * hh + 1] + bs1) * sc;
                if (MODE == 0) {
                    int hd = c0 >> 6, d = c0 & 63;
                    int b = row >> 11, s = row & (SEQ - 1);
                    size_t idx = ((((size_t)b * NHEAD + hd) * SEQ) + s) * DK + d;
                    if (z == 0) {
                        uint32_t hv, lv;
                        pack_hl(v0, v1, hv, lv);
                        *(uint32_t*)&g_qh[idx] = hv;
                        *(uint32_t*)&g_ql[idx] = lv;
                    } else if (z == 1) {
                        *(uint32_t*)&g_k[idx] = pack_h(v0, v1);
                    } else {
                        *(uint32_t*)&g_v[idx] = pack_h(v0, v1);
                    }
                } else {
                    float2 o = make_float2(v0, v1);
                    *(float2*)&Cout[(size_t)row * DMODEL + c0] = o;
                }
            }
        }
    }
}

// ---------------------------------------------------------------------------
// Flash attention: S = (Qh+Ql)K^T;  O = (Ph+Pl)·V. 3-buffer KV ring, 2 CTAs/SM.
// ---------------------------------------------------------------------------
#define ASTRIDE 144
#define AQBUF (128*ASTRIDE)          // 18432
#define AKBUF (64*ASTRIDE)           // 9216
#define ASTAGE (2*AKBUF)             // K, V
#define ANSTG 3
#define ATT_SMEM (2*AQBUF + ANSTG*ASTAGE)   // 92160

__device__ __forceinline__ void a_load_kv(uint32_t sb, int stg, int bh, int kt, int tid)
{
    uint32_t base = sb + 2 * AQBUF + stg * ASTAGE;
#pragma unroll
    for (int j = 0; j < 4; j++) {
        int g = tid + 256 * j;
        int buf = g >> 9;             // 0:K 1:V
        int cid = g & 511;
        int row = cid >> 3;
        int ch  = cid & 7;
        const __half* src = buf ? g_v : g_k;
        const void* gp = src + ((size_t)bh * SEQ + kt * 64 + row) * DK + ch * 8;
        cp_async16(base + buf * AKBUF + row * ASTRIDE + ch * 16, gp);
    }
}

__global__ __launch_bounds__(256, 2)
void attn_mma_kernel()
{
    extern __shared__ __align__(128) char sma[];
    const uint32_t sb = smem_u32(sma);
    const int tid = threadIdx.x;
    const int lane = tid & 31;
    const int wid = tid >> 5;
    const int bh = blockIdx.y;
    const int q0 = blockIdx.x * 128;

#pragma unroll
    for (int j = 0; j < 8; j++) {
        int g = tid + 256 * j;
        int buf = g >> 10;           // 0:Qh 1:Ql
        int cid = g & 1023;
        int row = cid >> 3;
        int ch  = cid & 7;
        const __half* src = buf ? g_ql : g_qh;
        const void* gp = src + ((size_t)bh * SEQ + q0 + row) * DK + ch * 8;
        cp_async16(sb + buf * AQBUF + row * ASTRIDE + ch * 16, gp);
    }
    CP_COMMIT();
    a_load_kv(sb, 0, bh, 0, tid); CP_COMMIT();
    a_load_kv(sb, 1, bh, 1, tid); CP_COMMIT();

    const uint32_t a_row = (lane & 15);
    const uint32_t a_k8  = (lane >> 4) << 3;
    const uint32_t b_row = ((lane >> 4) << 3) + (lane & 7);
    const uint32_t b_k8  = ((lane >> 3) & 1) << 3;
    const uint32_t v_row = (((lane >> 3) & 1) << 3) + (lane & 7);
    const uint32_t v_c8  = (lane >> 4) << 3;
    const int wq = wid * 16;

    float o[8][4];
#pragma unroll
    for (int i = 0; i < 8; i++)
#pragma unroll
        for (int k = 0; k < 4; k++) o[i][k] = 0.f;
    float m0 = -INFINITY, m1 = -INFINITY, l0 = 0.f, l1 = 0.f;

    const int NT = SEQ / 64;   // 32
    for (int it = 0; it < NT; it++) {
        if (it == NT - 1) { CP_WAIT(0); } else { CP_WAIT(1); }
        __syncthreads();

        if (it + 2 < NT) {
            a_load_kv(sb, (it + 2) % ANSTG, bh, it + 2, tid);
            CP_COMMIT();
        }

        uint32_t kb = sb + 2 * AQBUF + (it % ANSTG) * ASTAGE;

        float s[8][4];
#pragma unroll
        for (int i = 0; i < 8; i++)
#pragma unroll
            for (int k = 0; k < 4; k++) s[i][k] = 0.f;

#pragma unroll
        for (int ks = 0; ks < 4; ks++) {
            uint32_t ra = sb + (wq + a_row) * ASTRIDE + (ks * 16 + a_k8) * 2;
            uint32_t Qh[4], Ql[4];
            ldsm4(ra, Qh);
            ldsm4(ra + AQBUF, Ql);
#pragma unroll
            for (int np = 0; np < 4; np++) {
                uint32_t rb = kb + (np * 16 + b_row) * ASTRIDE + (ks * 16 + b_k8) * 2;
                uint32_t Kf[4];
                ldsm4(rb, Kf);
#pragma unroll
                for (int nn = 0; nn < 2; nn++)
                    mma_f16(s[np * 2 + nn], Qh, Kf + 2 * nn);
#pragma unroll
                for (int nn = 0; nn < 2; nn++)
                    mma_f16(s[np * 2 + nn], Ql, Kf + 2 * nn);
            }
        }

        float mx0 = -INFINITY, mx1 = -INFINITY;
#pragma unroll
        for (int i = 0; i < 8; i++) {
            mx0 = fmaxf(mx0, fmaxf(s[i][0], s[i][1]));
            mx1 = fmaxf(mx1, fmaxf(s[i][2], s[i][3]));
        }
        mx0 = fmaxf(mx0, __shfl_xor_sync(0xffffffffu, mx0, 1));
        mx0 = fmaxf(mx0, __shfl_xor_sync(0xffffffffu, mx0, 2));
        mx1 = fmaxf(mx1, __shfl_xor_sync(0xffffffffu, mx1, 1));
        mx1 = fmaxf(mx1, __shfl_xor_sync(0xffffffffu, mx1, 2));

        float mn0 = fmaxf(m0, mx0), mn1 = fmaxf(m1, mx1);
        float al0 = __expf(m0 - mn0), al1 = __expf(m1 - mn1);
        m0 = mn0; m1 = mn1;

        float rs0 = 0.f, rs1 = 0.f;
#pragma unroll
        for (int i = 0; i < 8; i++) {
            s[i][0] = __expf(s[i][0] - mn0);
            s[i][1] = __expf(s[i][1] - mn0);
            s[i][2] = __expf(s[i][2] - mn1);
            s[i][3] = __expf(s[i][3] - mn1);
            rs0 += s[i][0] + s[i][1];
            rs1 += s[i][2] + s[i][3];
        }
        rs0 += __shfl_xor_sync(0xffffffffu, rs0, 1);
        rs0 += __shfl_xor_sync(0xffffffffu, rs0, 2);
        rs1 += __shfl_xor_sync(0xffffffffu, rs1, 1);
        rs1 += __shfl_xor_sync(0xffffffffu, rs1, 2);
        l0 = l0 * al0 + rs0;
        l1 = l1 * al1 + rs1;
#pragma unroll
        for (int i = 0; i < 8; i++) {
            o[i][0] *= al0; o[i][1] *= al0;
            o[i][2] *= al1; o[i][3] *= al1;
        }

#pragma unroll
        for (int j = 0; j < 4; j++) {
            uint32_t Ph[4], Pl[4];
            pack_hl(s[2*j][0],   s[2*j][1],   Ph[0], Pl[0]);
            pack_hl(s[2*j][2],   s[2*j][3],   Ph[1], Pl[1]);
            pack_hl(s[2*j+1][0], s[2*j+1][1], Ph[2], Pl[2]);
            pack_hl(s[2*j+1][2], s[2*j+1][3], Ph[3], Pl[3]);
#pragma unroll
            for (int np = 0; np < 4; np++) {
                uint32_t rv = kb + AKBUF + (j * 16 + v_row) * ASTRIDE
                              + (np * 16 + v_c8) * 2;
                uint32_t Vf[4];
                ldsm4t(rv, Vf);
#pragma unroll
                for (int nn = 0; nn < 2; nn++)
                    mma_f16(o[np * 2 + nn], Ph, Vf + 2 * nn);
#pragma unroll
                for (int nn = 0; nn < 2; nn++)
                    mma_f16(o[np * 2 + nn], Pl, Vf + 2 * nn);
            }
        }
    }

    // epilogue: x hi/lo
    float inv0 = 1.0f / l0, inv1 = 1.0f / l1;
    const int b = bh >> 4;
    const int h = bh & (NHEAD - 1);
    const int qrow = q0 + wid * 16 + (lane >> 2);
#pragma unroll
    for (int nf = 0; nf < 8; nf++) {
        int d = h * DK + nf * 8 + (lane & 3) * 2;
        uint32_t hv, lv;
        size_t idx0 = ((size_t)b * SEQ + qrow) * DMODEL + d;
        pack_hl(o[nf][0] * inv0, o[nf][1] * inv0, hv, lv);
        *(uint32_t*)&g_xh[idx0] = hv;
        *(uint32_t*)&g_xl[idx0] = lv;
        size_t idx1 = ((size_t)b * SEQ + qrow + 8) * DMODEL + d;
        pack_hl(o[nf][2] * inv1, o[nf][3] * inv1, hv, lv);
        *(uint32_t*)&g_xh[idx1] = hv;
        *(uint32_t*)&g_xl[idx1] = lv;
    }
}

// ---------------------------------------------------------------------------
extern "C" void kernel_launch(void* const* d_in, const int* in_sizes, int n_in,
                              void* d_out, int out_size)
{
    (void)in_sizes; (void)n_in; (void)out_size;
    const float* query = (const float*)d_in[0];
    const float* key   = (const float*)d_in[1];
    const float* value = (const float*)d_in[2];
    const float* Wq = (const float*)d_in[3];
    const float* bq = (const float*)d_in[4];
    const float* Wk = (const float*)d_in[5];
    const float* bk = (const float*)d_in[6];
    const float* Wv = (const float*)d_in[7];
    const float* bv = (const float*)d_in[8];
    const float* Wo = (const float*)d_in[9];
    const float* bo = (const float*)d_in[10];
    float* out = (float*)d_out;

    cudaFuncSetAttribute(gemm_mma_kernel<0>, cudaFuncAttributeMaxDynamicSharedMemorySize,
                         GEMM_SMEM0);
    cudaFuncSetAttribute(gemm_mma_kernel<1>, cudaFuncAttributeMaxDynamicSharedMemorySize,
                         GEMM_SMEM1);
    cudaFuncSetAttribute(attn_mma_kernel, cudaFuncAttributeMaxDynamicSharedMemorySize,
                         ATT_SMEM);

    const int nA4 = (int)(ACTN / 4);
    const int nW4 = (int)(WN / 4);

    cvt_w_kernel<<<dim3(nW4 / 256, 4), 256>>>(Wq, Wk, Wv, Wo, nW4);
    cvt_act_kernel<<<dim3(nA4 / 256, 3), 256>>>(query, key, value, nA4);

    gemm_mma_kernel<0><<<dim3(8, 64, 3), 256, GEMM_SMEM0>>>(bq, bk, bv, nullptr);

    attn_mma_kernel<<<dim3(SEQ / 128, BATCH * NHEAD), 256, ATT_SMEM>>>();

    gemm_mma_kernel<1><<<dim3(8, 64, 1), 256, GEMM_SMEM1>>>(bo, bo, bo, out);
}

// round 14
// speedup vs baseline: 1.5061x; 1.5061x over previous
#include <cuda_runtime.h>
#include <cuda_fp16.h>
#include <math.h>
#include <stdint.h>

#define NHEAD 16
#define DK 64
#define DMODEL 1024
#define BATCH 4
#define SEQ 2048
#define MTOT (BATCH*SEQ)                  // 8192
#define ACTN ((size_t)MTOT*DMODEL)
#define WN   ((size_t)DMODEL*DMODEL)
#define HS   ((size_t)BATCH*NHEAD*SEQ*DK)

// inputs single-rounded fp16 (3 slots: q,k,v); x (attn out) split hi/lo
__device__ __half g_a [3*ACTN];
__device__ __half g_xh[ACTN];
__device__ __half g_xl[ACTN];
__device__ __half g_w [4*WN];
__device__ __half g_qh[HS], g_ql[HS];     // Q split (scaled by 1/8)
__device__ __half g_k [HS];               // K single-rounded
__device__ __half g_v [HS];               // V single-rounded

// ---------------- helpers ----------------
__device__ __forceinline__ uint32_t smem_u32(const void* p) {
    uint32_t a;
    asm("{ .reg .u64 t; cvta.to.shared.u64 t, %1; cvt.u32.u64 %0, t; }" : "=r"(a) : "l"(p));
    return a;
}
__device__ __forceinline__ void cp_async16(uint32_t dst, const void* src) {
    asm volatile("cp.async.cg.shared.global [%0], [%1], 16;" :: "r"(dst), "l"(src));
}
#define CP_COMMIT() asm volatile("cp.async.commit_group;" ::: "memory")
#define CP_WAIT(n)  asm volatile("cp.async.wait_group %0;" :: "n"(n) : "memory")

__device__ __forceinline__ void ldsm4(uint32_t a, uint32_t* r) {
    asm volatile("ldmatrix.sync.aligned.m8n8.x4.shared.b16 {%0,%1,%2,%3}, [%4];"
        : "=r"(r[0]), "=r"(r[1]), "=r"(r[2]), "=r"(r[3]) : "r"(a));
}
__device__ __forceinline__ void ldsm4t(uint32_t a, uint32_t* r) {
    asm volatile("ldmatrix.sync.aligned.m8n8.x4.trans.shared.b16 {%0,%1,%2,%3}, [%4];"
        : "=r"(r[0]), "=r"(r[1]), "=r"(r[2]), "=r"(r[3]) : "r"(a));
}
__device__ __forceinline__ void mma_f16(float* c, const uint32_t* a, const uint32_t* b) {
    asm volatile("mma.sync.aligned.m16n8k16.row.col.f32.f16.f16.f32 "
        "{%0,%1,%2,%3}, {%4,%5,%6,%7}, {%8,%9}, {%0,%1,%2,%3};"
        : "+f"(c[0]), "+f"(c[1]), "+f"(c[2]), "+f"(c[3])
        : "r"(a[0]), "r"(a[1]), "r"(a[2]), "r"(a[3]), "r"(b[0]), "r"(b[1]));
}
__device__ __forceinline__ uint32_t pack_h(float p0, float p1) {
    __half2 hv = __floats2half2_rn(p0, p1);
    return *(uint32_t*)&hv;
}
__device__ __forceinline__ void pack_hl(float p0, float p1, uint32_t& h, uint32_t& l) {
    __half2 hv = __floats2half2_rn(p0, p1);
    __half2 lv = __floats2half2_rn(p0 - __low2float(hv), p1 - __high2float(hv));
    h = *(uint32_t*)&hv;
    l = *(uint32_t*)&lv;
}

// ---------------------------------------------------------------------------
// fp32 -> fp16 single-round convert, acts + weights in ONE launch.
// ---------------------------------------------------------------------------
__global__ void cvt_all_kernel(const float* __restrict__ q, const float* __restrict__ k,
                               const float* __restrict__ v,
                               const float* __restrict__ w0, const float* __restrict__ w1,
                               const float* __restrict__ w2, const float* __restrict__ w3,
                               int nA4, int nW4)
{
    int z = blockIdx.y;
    int i = blockIdx.x * blockDim.x + threadIdx.x;
    const float* src;
    __half* dst;
    if (z < 3) {
        if (i >= nA4) return;
        src = (z == 0) ? q : (z == 1) ? k : v;
        dst = g_a + (size_t)z * ACTN;
    } else {
        if (i >= nW4) return;
        int w = z - 3;
        src = (w == 0) ? w0 : (w == 1) ? w1 : (w == 2) ? w2 : w3;
        dst = g_w + (size_t)w * WN;
    }
    float4 vv = ((const float4*)src)[i];
    ((uint32_t*)dst)[2*i]   = pack_h(vv.x, vv.y);
    ((uint32_t*)dst)[2*i+1] = pack_h(vv.z, vv.w);
}

// ---------------------------------------------------------------------------
// GEMM template. MODE 0: QKV, 1-term, 4-stage pipeline (pf=3).
//                MODE 1: final, 2-term, 3-stage pipeline (pf=2).
// CTA 128x128, K-chunk 32, 2 CTAs/SM. 8 warps 4(M)x2(N), warp 32x64.
// ---------------------------------------------------------------------------
#define GKC 32
#define GSTRIDE 80
#define GA_BUF (128*GSTRIDE)             // 10240
#define GSTAGE0 (2*GA_BUF)               // A, W        = 20480
#define GSTAGE1 (3*GA_BUF)               // Xh, Xl, W   = 30720
#define GEMM_SMEM0 (4*GSTAGE0)           // 81920
#define GEMM_SMEM1 (3*GSTAGE1)           // 92160

template<int MODE>
__device__ __forceinline__ void g_load_stage(uint32_t base,
                                             const __half* A0, const __half* A1,
                                             const __half* W_g,
                                             int bm, int bn, int k0, int tid)
{
    constexpr int NCH = (MODE == 0) ? 4 : 6;
#pragma unroll
    for (int j = 0; j < NCH; j++) {
        int g = tid + 256 * j;
        int buf = g >> 9;
        int cid = g & 511;
        int row = cid >> 2;
        int ch  = cid & 3;
        const __half* src;
        int rbase;
        if (MODE == 0) {
            src = buf ? W_g : A0;
            rbase = buf ? bn : bm;
        } else {
            src = (buf == 0) ? A0 : (buf == 1) ? A1 : W_g;
            rbase = (buf < 2) ? bm : bn;
        }
        cp_async16(base + buf * GA_BUF + row * GSTRIDE + ch * 16,
                   src + (size_t)(rbase + row) * DMODEL + k0 + ch * 8);
    }
}

template<int MODE>
__global__ __launch_bounds__(256, 2)
void gemm_mma_kernel(const float* __restrict__ b0, const float* __restrict__ b1,
                     const float* __restrict__ b2, float* __restrict__ Cout)
{
    extern __shared__ __align__(128) char smg[];
    const uint32_t sb = smem_u32(smg);
    const int tid = threadIdx.x;
    const int lane = tid & 31;
    const int wid = tid >> 5;
    const int wr = (wid >> 1) * 32;
    const int wn = (wid & 1) * 64;
    const int bm = blockIdx.y * 128;
    const int bn = blockIdx.x * 128;
    const int z = blockIdx.z;

    constexpr int NSTG  = (MODE == 0) ? 4 : 3;
    constexpr int STAGE = (MODE == 0) ? GSTAGE0 : GSTAGE1;
    constexpr int WOFF  = (MODE == 0) ? GA_BUF : 2 * GA_BUF;
    constexpr int PF    = NSTG - 1;          // prefetch distance < NSTG (R12 bug fix)

    const __half* A0 = (MODE == 0) ? g_a + (size_t)z * ACTN : g_xh;
    const __half* A1 = (MODE == 0) ? (const __half*)nullptr : g_xl;
    const __half* W_g = g_w + (size_t)((MODE == 0) ? z : 3) * WN;
    const float* bias = (MODE == 1) ? b0 : (z == 0) ? b0 : (z == 1) ? b1 : b2;

    float acc[2][8][4];
#pragma unroll
    for (int a = 0; a < 2; a++)
#pragma unroll
        for (int b = 0; b < 8; b++)
#pragma unroll
            for (int c = 0; c < 4; c++) acc[a][b][c] = 0.f;

    // prologue: PF stages in flight
#pragma unroll
    for (int p = 0; p < PF; p++) {
        g_load_stage<MODE>(sb + p * STAGE, A0, A1, W_g, bm, bn, p * GKC, tid);
        CP_COMMIT();
    }

    const int NIT = DMODEL / GKC;   // 32
    const uint32_t a_row = (lane & 15);
    const uint32_t a_k8  = (lane >> 4) << 3;
    const uint32_t b_row = ((lane >> 4) << 3) + (lane & 7);
    const uint32_t b_k8  = ((lane >> 3) & 1) << 3;

    for (int it = 0; it < NIT; it++) {
        int rem = NIT - 1 - it;
        int pend = (rem < PF - 1) ? rem : (PF - 1);
        if      (pend >= 2) { CP_WAIT(2); }
        else if (pend == 1) { CP_WAIT(1); }
        else                { CP_WAIT(0); }
        __syncthreads();

        if (it + PF < NIT) {
            g_load_stage<MODE>(sb + ((it + PF) % NSTG) * STAGE, A0, A1, W_g,
                               bm, bn, (it + PF) * GKC, tid);
            CP_COMMIT();
        }

        uint32_t base = sb + (it % NSTG) * STAGE;
#pragma unroll
        for (int ks = 0; ks < 2; ks++) {
            const int k0 = ks * 16;
            uint32_t Ah[2][4], Al[2][4], Bf[4][4];
#pragma unroll
            for (int mf = 0; mf < 2; mf++) {
                uint32_t ra = base + (wr + mf * 16 + a_row) * GSTRIDE + (k0 + a_k8) * 2;
                ldsm4(ra, Ah[mf]);
                if (MODE == 1) ldsm4(ra + GA_BUF, Al[mf]);
            }
#pragma unroll
            for (int np = 0; np < 4; np++) {
                uint32_t rb = base + WOFF + (wn + np * 16 + b_row) * GSTRIDE
                              + (k0 + b_k8) * 2;
                ldsm4(rb, Bf[np]);
            }
#pragma unroll
            for (int np = 0; np < 4; np++)
#pragma unroll
                for (int nn = 0; nn < 2; nn++)
#pragma unroll
                    for (int mf = 0; mf < 2; mf++)
                        mma_f16(acc[mf][np * 2 + nn], Ah[mf], Bf[np] + 2 * nn);
            if (MODE == 1) {
#pragma unroll
                for (int np = 0; np < 4; np++)
#pragma unroll
                    for (int nn = 0; nn < 2; nn++)
#pragma unroll
                        for (int mf = 0; mf < 2; mf++)
                            mma_f16(acc[mf][np * 2 + nn], Al[mf], Bf[np] + 2 * nn);
            }
        }
    }

    // epilogue
    const float sc = (MODE == 0 && z == 0) ? 0.125f : 1.0f;
#pragma unroll
    for (int mf = 0; mf < 2; mf++) {
#pragma unroll
        for (int nf = 0; nf < 8; nf++) {
            int r0 = bm + wr + mf * 16 + (lane >> 2);
            int c0 = bn + wn + nf * 8 + (lane & 3) * 2;
            float bs0 = bias[c0], bs1 = bias[c0 + 1];
#pragma unroll
            for (int hh = 0; hh < 2; hh++) {
                int row = r0 + 8 * hh;
                float v0 = (acc[mf][nf][2 * hh + 0] + bs0) * sc;
                float v1 = (acc[mf][nf][2 * hh + 1] + bs1) * sc;
                if (MODE == 0) {
                    int hd = c0 >> 6, d = c0 & 63;
                    int b = row >> 11, s = row & (SEQ - 1);
                    size_t idx = ((((size_t)b * NHEAD + hd) * SEQ) + s) * DK + d;
                    if (z == 0) {
                        uint32_t hv, lv;
                        pack_hl(v0, v1, hv, lv);
                        *(uint32_t*)&g_qh[idx] = hv;
                        *(uint32_t*)&g_ql[idx] = lv;
                    } else if (z == 1) {
                        *(uint32_t*)&g_k[idx] = pack_h(v0, v1);
                    } else {
                        *(uint32_t*)&g_v[idx] = pack_h(v0, v1);
                    }
                } else {
                    float2 o = make_float2(v0, v1);
                    *(float2*)&Cout[(size_t)row * DMODEL + c0] = o;
                }
            }
        }
    }
}

// ---------------------------------------------------------------------------
// Flash attention: S = (Qh+Ql)K^T;  O = (Ph+Pl)·V. 3-buffer KV ring, 2 CTAs/SM.
// ---------------------------------------------------------------------------
#define ASTRIDE 144
#define AQBUF (128*ASTRIDE)          // 18432
#define AKBUF (64*ASTRIDE)           // 9216
#define ASTAGE (2*AKBUF)             // K, V
#define ANSTG 3
#define ATT_SMEM (2*AQBUF + ANSTG*ASTAGE)   // 92160

__device__ __forceinline__ void a_load_kv(uint32_t sb, int stg, int bh, int kt, int tid)
{
    uint32_t base = sb + 2 * AQBUF + stg * ASTAGE;
#pragma unroll
    for (int j = 0; j < 4; j++) {
        int g = tid + 256 * j;
        int buf = g >> 9;             // 0:K 1:V
        int cid = g & 511;
        int row = cid >> 3;
        int ch  = cid & 7;
        const __half* src = buf ? g_v : g_k;
        const void* gp = src + ((size_t)bh * SEQ + kt * 64 + row) * DK + ch * 8;
        cp_async16(base + buf * AKBUF + row * ASTRIDE + ch * 16, gp);
    }
}

__global__ __launch_bounds__(256, 2)
void attn_mma_kernel()
{
    extern __shared__ __align__(128) char sma[];
    const uint32_t sb = smem_u32(sma);
    const int tid = threadIdx.x;
    const int lane = tid & 31;
    const int wid = tid >> 5;
    const int bh = blockIdx.y;
    const int q0 = blockIdx.x * 128;

#pragma unroll
    for (int j = 0; j < 8; j++) {
        int g = tid + 256 * j;
        int buf = g >> 10;           // 0:Qh 1:Ql
        int cid = g & 1023;
        int row = cid >> 3;
        int ch  = cid & 7;
        const __half* src = buf ? g_ql : g_qh;
        const void* gp = src + ((size_t)bh * SEQ + q0 + row) * DK + ch * 8;
        cp_async16(sb + buf * AQBUF + row * ASTRIDE + ch * 16, gp);
    }
    CP_COMMIT();
    a_load_kv(sb, 0, bh, 0, tid); CP_COMMIT();
    a_load_kv(sb, 1, bh, 1, tid); CP_COMMIT();

    const uint32_t a_row = (lane & 15);
    const uint32_t a_k8  = (lane >> 4) << 3;
    const uint32_t b_row = ((lane >> 4) << 3) + (lane & 7);
    const uint32_t b_k8  = ((lane >> 3) & 1) << 3;
    const uint32_t v_row = (((lane >> 3) & 1) << 3) + (lane & 7);
    const uint32_t v_c8  = (lane >> 4) << 3;
    const int wq = wid * 16;

    float o[8][4];
#pragma unroll
    for (int i = 0; i < 8; i++)
#pragma unroll
        for (int k = 0; k < 4; k++) o[i][k] = 0.f;
    float m0 = -INFINITY, m1 = -INFINITY, l0 = 0.f, l1 = 0.f;

    const int NT = SEQ / 64;   // 32
    for (int it = 0; it < NT; it++) {
        if (it == NT - 1) { CP_WAIT(0); } else { CP_WAIT(1); }
        __syncthreads();

        if (it + 2 < NT) {
            a_load_kv(sb, (it + 2) % ANSTG, bh, it + 2, tid);
            CP_COMMIT();
        }

        uint32_t kb = sb + 2 * AQBUF + (it % ANSTG) * ASTAGE;

        float s[8][4];
#pragma unroll
        for (int i = 0; i < 8; i++)
#pragma unroll
            for (int k = 0; k < 4; k++) s[i][k] = 0.f;

#pragma unroll
        for (int ks = 0; ks < 4; ks++) {
            uint32_t ra = sb + (wq + a_row) * ASTRIDE + (ks * 16 + a_k8) * 2;
            uint32_t Qh[4], Ql[4];
            ldsm4(ra, Qh);
            ldsm4(ra + AQBUF, Ql);
#pragma unroll
            for (int np = 0; np < 4; np++) {
                uint32_t rb = kb + (np * 16 + b_row) * ASTRIDE + (ks * 16 + b_k8) * 2;
                uint32_t Kf[4];
                ldsm4(rb, Kf);
#pragma unroll
                for (int nn = 0; nn < 2; nn++)
                    mma_f16(s[np * 2 + nn], Qh, Kf + 2 * nn);
#pragma unroll
                for (int nn = 0; nn < 2; nn++)
                    mma_f16(s[np * 2 + nn], Ql, Kf + 2 * nn);
            }
        }

        float mx0 = -INFINITY, mx1 = -INFINITY;
#pragma unroll
        for (int i = 0; i < 8; i++) {
            mx0 = fmaxf(mx0, fmaxf(s[i][0], s[i][1]));
            mx1 = fmaxf(mx1, fmaxf(s[i][2], s[i][3]));
        }
        mx0 = fmaxf(mx0, __shfl_xor_sync(0xffffffffu, mx0, 1));
        mx0 = fmaxf(mx0, __shfl_xor_sync(0xffffffffu, mx0, 2));
        mx1 = fmaxf(mx1, __shfl_xor_sync(0xffffffffu, mx1, 1));
        mx1 = fmaxf(mx1, __shfl_xor_sync(0xffffffffu, mx1, 2));

        float mn0 = fmaxf(m0, mx0), mn1 = fmaxf(m1, mx1);
        float al0 = __expf(m0 - mn0), al1 = __expf(m1 - mn1);
        m0 = mn0; m1 = mn1;

        float rs0 = 0.f, rs1 = 0.f;
#pragma unroll
        for (int i = 0; i < 8; i++) {
            s[i][0] = __expf(s[i][0] - mn0);
            s[i][1] = __expf(s[i][1] - mn0);
            s[i][2] = __expf(s[i][2] - mn1);
            s[i][3] = __expf(s[i][3] - mn1);
            rs0 += s[i][0] + s[i][1];
            rs1 += s[i][2] + s[i][3];
        }
        rs0 += __shfl_xor_sync(0xffffffffu, rs0, 1);
        rs0 += __shfl_xor_sync(0xffffffffu, rs0, 2);
        rs1 += __shfl_xor_sync(0xffffffffu, rs1, 1);
        rs1 += __shfl_xor_sync(0xffffffffu, rs1, 2);
        l0 = l0 * al0 + rs0;
        l1 = l1 * al1 + rs1;
#pragma unroll
        for (int i = 0; i < 8; i++) {
            o[i][0] *= al0; o[i][1] *= al0;
            o[i][2] *= al1; o[i][3] *= al1;
        }

#pragma unroll
        for (int j = 0; j < 4; j++) {
            uint32_t Ph[4], Pl[4];
            pack_hl(s[2*j][0],   s[2*j][1],   Ph[0], Pl[0]);
            pack_hl(s[2*j][2],   s[2*j][3],   Ph[1], Pl[1]);
            pack_hl(s[2*j+1][0], s[2*j+1][1], Ph[2], Pl[2]);
            pack_hl(s[2*j+1][2], s[2*j+1][3], Ph[3], Pl[3]);
#pragma unroll
            for (int np = 0; np < 4; np++) {
                uint32_t rv = kb + AKBUF + (j * 16 + v_row) * ASTRIDE
                              + (np * 16 + v_c8) * 2;
                uint32_t Vf[4];
                ldsm4t(rv, Vf);
#pragma unroll
                for (int nn = 0; nn < 2; nn++)
                    mma_f16(o[np * 2 + nn], Ph, Vf + 2 * nn);
#pragma unroll
                for (int nn = 0; nn < 2; nn++)
                    mma_f16(o[np * 2 + nn], Pl, Vf + 2 * nn);
            }
        }
    }

    // epilogue: x hi/lo
    float inv0 = 1.0f / l0, inv1 = 1.0f / l1;
    const int b = bh >> 4;
    const int h = bh & (NHEAD - 1);
    const int qrow = q0 + wid * 16 + (lane >> 2);
#pragma unroll
    for (int nf = 0; nf < 8; nf++) {
        int d = h * DK + nf * 8 + (lane & 3) * 2;
        uint32_t hv, lv;
        size_t idx0 = ((size_t)b * SEQ + qrow) * DMODEL + d;
        pack_hl(o[nf][0] * inv0, o[nf][1] * inv0, hv, lv);
        *(uint32_t*)&g_xh[idx0] = hv;
        *(uint32_t*)&g_xl[idx0] = lv;
        size_t idx1 = ((size_t)b * SEQ + qrow + 8) * DMODEL + d;
        pack_hl(o[nf][2] * inv1, o[nf][3] * inv1, hv, lv);
        *(uint32_t*)&g_xh[idx1] = hv;
        *(uint32_t*)&g_xl[idx1] = lv;
    }
}

// ---------------------------------------------------------------------------
extern "C" void kernel_launch(void* const* d_in, const int* in_sizes, int n_in,
                              void* d_out, int out_size)
{
    (void)in_sizes; (void)n_in; (void)out_size;
    const float* query = (const float*)d_in[0];
    const float* key   = (const float*)d_in[1];
    const float* value = (const float*)d_in[2];
    const float* Wq = (const float*)d_in[3];
    const float* bq = (const float*)d_in[4];
    const float* Wk = (const float*)d_in[5];
    const float* bk = (const float*)d_in[6];
    const float* Wv = (const float*)d_in[7];
    const float* bv = (const float*)d_in[8];
    const float* Wo = (const float*)d_in[9];
    const float* bo = (const float*)d_in[10];
    float* out = (float*)d_out;

    cudaFuncSetAttribute(gemm_mma_kernel<0>, cudaFuncAttributeMaxDynamicSharedMemorySize,
                         GEMM_SMEM0);
    cudaFuncSetAttribute(gemm_mma_kernel<1>, cudaFuncAttributeMaxDynamicSharedMemorySize,
                         GEMM_SMEM1);
    cudaFuncSetAttribute(attn_mma_kernel, cudaFuncAttributeMaxDynamicSharedMemorySize,
                         ATT_SMEM);

    const int nA4 = (int)(ACTN / 4);
    const int nW4 = (int)(WN / 4);

    cvt_all_kernel<<<dim3(nA4 / 256, 7), 256>>>(query, key, value, Wq, Wk, Wv, Wo,
                                                nA4, nW4);

    gemm_mma_kernel<0><<<dim3(8, 64, 3), 256, GEMM_SMEM0>>>(bq, bk, bv, nullptr);

    attn_mma_kernel<<<dim3(SEQ / 128, BATCH * NHEAD), 256, ATT_SMEM>>>();

    gemm_mma_kernel<1><<<dim3(8, 64, 1), 256, GEMM_SMEM1>>>(bo, bo, bo, out);
}

// round 15
// speedup vs baseline: 1.6294x; 1.0819x over previous
#include <cuda_runtime.h>
#include <cuda_fp16.h>
#include <math.h>
#include <stdint.h>

#define NHEAD 16
#define DK 64
#define DMODEL 1024
#define BATCH 4
#define SEQ 2048
#define MTOT (BATCH*SEQ)                  // 8192
#define ACTN ((size_t)MTOT*DMODEL)
#define WN   ((size_t)DMODEL*DMODEL)
#define HS   ((size_t)BATCH*NHEAD*SEQ*DK)

// inputs single-rounded fp16 (3 slots: q,k,v); x (attn out) single-rounded
__device__ __half g_a [3*ACTN];
__device__ __half g_x [ACTN];
__device__ __half g_w [4*WN];
__device__ __half g_qh[HS], g_ql[HS];     // Q split (scaled by 1/8)
__device__ __half g_k [HS];               // K single-rounded
__device__ __half g_v [HS];               // V single-rounded

// ---------------- helpers ----------------
__device__ __forceinline__ uint32_t smem_u32(const void* p) {
    uint32_t a;
    asm("{ .reg .u64 t; cvta.to.shared.u64 t, %1; cvt.u32.u64 %0, t; }" : "=r"(a) : "l"(p));
    return a;
}
__device__ __forceinline__ void cp_async16(uint32_t dst, const void* src) {
    asm volatile("cp.async.cg.shared.global [%0], [%1], 16;" :: "r"(dst), "l"(src));
}
#define CP_COMMIT() asm volatile("cp.async.commit_group;" ::: "memory")
#define CP_WAIT(n)  asm volatile("cp.async.wait_group %0;" :: "n"(n) : "memory")

__device__ __forceinline__ void ldsm4(uint32_t a, uint32_t* r) {
    asm volatile("ldmatrix.sync.aligned.m8n8.x4.shared.b16 {%0,%1,%2,%3}, [%4];"
        : "=r"(r[0]), "=r"(r[1]), "=r"(r[2]), "=r"(r[3]) : "r"(a));
}
__device__ __forceinline__ void ldsm4t(uint32_t a, uint32_t* r) {
    asm volatile("ldmatrix.sync.aligned.m8n8.x4.trans.shared.b16 {%0,%1,%2,%3}, [%4];"
        : "=r"(r[0]), "=r"(r[1]), "=r"(r[2]), "=r"(r[3]) : "r"(a));
}
__device__ __forceinline__ void mma_f16(float* c, const uint32_t* a, const uint32_t* b) {
    asm volatile("mma.sync.aligned.m16n8k16.row.col.f32.f16.f16.f32 "
        "{%0,%1,%2,%3}, {%4,%5,%6,%7}, {%8,%9}, {%0,%1,%2,%3};"
        : "+f"(c[0]), "+f"(c[1]), "+f"(c[2]), "+f"(c[3])
        : "r"(a[0]), "r"(a[1]), "r"(a[2]), "r"(a[3]), "r"(b[0]), "r"(b[1]));
}
__device__ __forceinline__ uint32_t pack_h(float p0, float p1) {
    __half2 hv = __floats2half2_rn(p0, p1);
    return *(uint32_t*)&hv;
}
__device__ __forceinline__ void pack_hl(float p0, float p1, uint32_t& h, uint32_t& l) {
    __half2 hv = __floats2half2_rn(p0, p1);
    __half2 lv = __floats2half2_rn(p0 - __low2float(hv), p1 - __high2float(hv));
    h = *(uint32_t*)&hv;
    l = *(uint32_t*)&lv;
}

// ---------------------------------------------------------------------------
// fp32 -> fp16 single-round convert, acts + weights in ONE launch.
// ---------------------------------------------------------------------------
__global__ void cvt_all_kernel(const float* __restrict__ q, const float* __restrict__ k,
                               const float* __restrict__ v,
                               const float* __restrict__ w0, const float* __restrict__ w1,
                               const float* __restrict__ w2, const float* __restrict__ w3,
                               int nA4, int nW4)
{
    int z = blockIdx.y;
    int i = blockIdx.x * blockDim.x + threadIdx.x;
    const float* src;
    __half* dst;
    if (z < 3) {
        if (i >= nA4) return;
        src = (z == 0) ? q : (z == 1) ? k : v;
        dst = g_a + (size_t)z * ACTN;
    } else {
        if (i >= nW4) return;
        int w = z - 3;
        src = (w == 0) ? w0 : (w == 1) ? w1 : (w == 2) ? w2 : w3;
        dst = g_w + (size_t)w * WN;
    }
    float4 vv = ((const float4*)src)[i];
    ((uint32_t*)dst)[2*i]   = pack_h(vv.x, vv.y);
    ((uint32_t*)dst)[2*i+1] = pack_h(vv.z, vv.w);
}

// ---------------------------------------------------------------------------
// GEMM: 1-term fp16 (A single x W single), 4-stage pipeline (pf=3).
// MODE 0: QKV fused (z selects act slot / W slot / bias / dest).
// MODE 1: final projection (A = g_x, W slot 3, fp32 out).
// CTA 128x128, K-chunk 32, 2 CTAs/SM. 8 warps 4(M)x2(N), warp 32x64.
// ---------------------------------------------------------------------------
#define GKC 32
#define GSTRIDE 80
#define GA_BUF (128*GSTRIDE)             // 10240
#define GSTAGE (2*GA_BUF)                // A, W = 20480
#define GNSTG 4
#define GEMM_SMEM (GNSTG*GSTAGE)         // 81920
#define GPF 3

__device__ __forceinline__ void g_load_stage(uint32_t base,
                                             const __half* A_g, const __half* W_g,
                                             int bm, int bn, int k0, int tid)
{
#pragma unroll
    for (int j = 0; j < 4; j++) {
        int g = tid + 256 * j;
        int buf = g >> 9;                 // 0:A 1:W
        int cid = g & 511;
        int row = cid >> 2;
        int ch  = cid & 3;
        const __half* src = buf ? W_g : A_g;
        int rbase = buf ? bn : bm;
        cp_async16(base + buf * GA_BUF + row * GSTRIDE + ch * 16,
                   src + (size_t)(rbase + row) * DMODEL + k0 + ch * 8);
    }
}

template<int MODE>
__global__ __launch_bounds__(256, 2)
void gemm_mma_kernel(const float* __restrict__ b0, const float* __restrict__ b1,
                     const float* __restrict__ b2, float* __restrict__ Cout)
{
    extern __shared__ __align__(128) char smg[];
    const uint32_t sb = smem_u32(smg);
    const int tid = threadIdx.x;
    const int lane = tid & 31;
    const int wid = tid >> 5;
    const int wr = (wid >> 1) * 32;
    const int wn = (wid & 1) * 64;
    const int bm = blockIdx.y * 128;
    const int bn = blockIdx.x * 128;
    const int z = blockIdx.z;

    const __half* A_g = (MODE == 0) ? g_a + (size_t)z * ACTN : g_x;
    const __half* W_g = g_w + (size_t)((MODE == 0) ? z : 3) * WN;
    const float* bias = (MODE == 1) ? b0 : (z == 0) ? b0 : (z == 1) ? b1 : b2;

    float acc[2][8][4];
#pragma unroll
    for (int a = 0; a < 2; a++)
#pragma unroll
        for (int b = 0; b < 8; b++)
#pragma unroll
            for (int c = 0; c < 4; c++) acc[a][b][c] = 0.f;

#pragma unroll
    for (int p = 0; p < GPF; p++) {
        g_load_stage(sb + p * GSTAGE, A_g, W_g, bm, bn, p * GKC, tid);
        CP_COMMIT();
    }

    const int NIT = DMODEL / GKC;   // 32
    const uint32_t a_row = (lane & 15);
    const uint32_t a_k8  = (lane >> 4) << 3;
    const uint32_t b_row = ((lane >> 4) << 3) + (lane & 7);
    const uint32_t b_k8  = ((lane >> 3) & 1) << 3;

    for (int it = 0; it < NIT; it++) {
        int rem = NIT - 1 - it;
        int pend = (rem < GPF - 1) ? rem : (GPF - 1);
        if      (pend >= 2) { CP_WAIT(2); }
        else if (pend == 1) { CP_WAIT(1); }
        else                { CP_WAIT(0); }
        __syncthreads();

        if (it + GPF < NIT) {
            g_load_stage(sb + ((it + GPF) % GNSTG) * GSTAGE, A_g, W_g,
                         bm, bn, (it + GPF) * GKC, tid);
            CP_COMMIT();
        }

        uint32_t base = sb + (it % GNSTG) * GSTAGE;
#pragma unroll
        for (int ks = 0; ks < 2; ks++) {
            const int k0 = ks * 16;
            uint32_t Af[2][4], Bf[4][4];
#pragma unroll
            for (int mf = 0; mf < 2; mf++) {
                uint32_t ra = base + (wr + mf * 16 + a_row) * GSTRIDE + (k0 + a_k8) * 2;
                ldsm4(ra, Af[mf]);
            }
#pragma unroll
            for (int np = 0; np < 4; np++) {
                uint32_t rb = base + GA_BUF + (wn + np * 16 + b_row) * GSTRIDE
                              + (k0 + b_k8) * 2;
                ldsm4(rb, Bf[np]);
            }
#pragma unroll
            for (int np = 0; np < 4; np++)
#pragma unroll
                for (int nn = 0; nn < 2; nn++)
#pragma unroll
                    for (int mf = 0; mf < 2; mf++)
                        mma_f16(acc[mf][np * 2 + nn], Af[mf], Bf[np] + 2 * nn);
        }
    }

    // epilogue
    const float sc = (MODE == 0 && z == 0) ? 0.125f : 1.0f;
#pragma unroll
    for (int mf = 0; mf < 2; mf++) {
#pragma unroll
        for (int nf = 0; nf < 8; nf++) {
            int r0 = bm + wr + mf * 16 + (lane >> 2);
            int c0 = bn + wn + nf * 8 + (lane & 3) * 2;
            float bs0 = bias[c0], bs1 = bias[c0 + 1];
#pragma unroll
            for (int hh = 0; hh < 2; hh++) {
                int row = r0 + 8 * hh;
                float v0 = (acc[mf][nf][2 * hh + 0] + bs0) * sc;
                float v1 = (acc[mf][nf][2 * hh + 1] + bs1) * sc;
                if (MODE == 0) {
                    int hd = c0 >> 6, d = c0 & 63;
                    int b = row >> 11, s = row & (SEQ - 1);
                    size_t idx = ((((size_t)b * NHEAD + hd) * SEQ) + s) * DK + d;
                    if (z == 0) {
                        uint32_t hv, lv;
                        pack_hl(v0, v1, hv, lv);
                        *(uint32_t*)&g_qh[idx] = hv;
                        *(uint32_t*)&g_ql[idx] = lv;
                    } else if (z == 1) {
                        *(uint32_t*)&g_k[idx] = pack_h(v0, v1);
                    } else {
                        *(uint32_t*)&g_v[idx] = pack_h(v0, v1);
                    }
                } else {
                    float2 o = make_float2(v0, v1);
                    *(float2*)&Cout[(size_t)row * DMODEL + c0] = o;
                }
            }
        }
    }
}

// ---------------------------------------------------------------------------
// Flash attention: S = (Qh+Ql)K^T;  O = (Ph+Pl)·V. 3-buffer KV ring, 2 CTAs/SM.
// Output x single-rounded into g_x.
// ---------------------------------------------------------------------------
#define ASTRIDE 144
#define AQBUF (128*ASTRIDE)          // 18432
#define AKBUF (64*ASTRIDE)           // 9216
#define ASTAGE (2*AKBUF)             // K, V
#define ANSTG 3
#define ATT_SMEM (2*AQBUF + ANSTG*ASTAGE)   // 92160

__device__ __forceinline__ void a_load_kv(uint32_t sb, int stg, int bh, int kt, int tid)
{
    uint32_t base = sb + 2 * AQBUF + stg * ASTAGE;
#pragma unroll
    for (int j = 0; j < 4; j++) {
        int g = tid + 256 * j;
        int buf = g >> 9;             // 0:K 1:V
        int cid = g & 511;
        int row = cid >> 3;
        int ch  = cid & 7;
        const __half* src = buf ? g_v : g_k;
        const void* gp = src + ((size_t)bh * SEQ + kt * 64 + row) * DK + ch * 8;
        cp_async16(base + buf * AKBUF + row * ASTRIDE + ch * 16, gp);
    }
}

__global__ __launch_bounds__(256, 2)
void attn_mma_kernel()
{
    extern __shared__ __align__(128) char sma[];
    const uint32_t sb = smem_u32(sma);
    const int tid = threadIdx.x;
    const int lane = tid & 31;
    const int wid = tid >> 5;
    const int bh = blockIdx.y;
    const int q0 = blockIdx.x * 128;

#pragma unroll
    for (int j = 0; j < 8; j++) {
        int g = tid + 256 * j;
        int buf = g >> 10;           // 0:Qh 1:Ql
        int cid = g & 1023;
        int row = cid >> 3;
        int ch  = cid & 7;
        const __half* src = buf ? g_ql : g_qh;
        const void* gp = src + ((size_t)bh * SEQ + q0 + row) * DK + ch * 8;
        cp_async16(sb + buf * AQBUF + row * ASTRIDE + ch * 16, gp);
    }
    CP_COMMIT();
    a_load_kv(sb, 0, bh, 0, tid); CP_COMMIT();
    a_load_kv(sb, 1, bh, 1, tid); CP_COMMIT();

    const uint32_t a_row = (lane & 15);
    const uint32_t a_k8  = (lane >> 4) << 3;
    const uint32_t b_row = ((lane >> 4) << 3) + (lane & 7);
    const uint32_t b_k8  = ((lane >> 3) & 1) << 3;
    const uint32_t v_row = (((lane >> 3) & 1) << 3) + (lane & 7);
    const uint32_t v_c8  = (lane >> 4) << 3;
    const int wq = wid * 16;

    float o[8][4];
#pragma unroll
    for (int i = 0; i < 8; i++)
#pragma unroll
        for (int k = 0; k < 4; k++) o[i][k] = 0.f;
    float m0 = -INFINITY, m1 = -INFINITY, l0 = 0.f, l1 = 0.f;

    const int NT = SEQ / 64;   // 32
    for (int it = 0; it < NT; it++) {
        if (it == NT - 1) { CP_WAIT(0); } else { CP_WAIT(1); }
        __syncthreads();

        if (it + 2 < NT) {
            a_load_kv(sb, (it + 2) % ANSTG, bh, it + 2, tid);
            CP_COMMIT();
        }

        uint32_t kb = sb + 2 * AQBUF + (it % ANSTG) * ASTAGE;

        float s[8][4];
#pragma unroll
        for (int i = 0; i < 8; i++)
#pragma unroll
            for (int k = 0; k < 4; k++) s[i][k] = 0.f;

#pragma unroll
        for (int ks = 0; ks < 4; ks++) {
            uint32_t ra = sb + (wq + a_row) * ASTRIDE + (ks * 16 + a_k8) * 2;
            uint32_t Qh[4], Ql[4];
            ldsm4(ra, Qh);
            ldsm4(ra + AQBUF, Ql);
#pragma unroll
            for (int np = 0; np < 4; np++) {
                uint32_t rb = kb + (np * 16 + b_row) * ASTRIDE + (ks * 16 + b_k8) * 2;
                uint32_t Kf[4];
                ldsm4(rb, Kf);
#pragma unroll
                for (int nn = 0; nn < 2; nn++)
                    mma_f16(s[np * 2 + nn], Qh, Kf + 2 * nn);
#pragma unroll
                for (int nn = 0; nn < 2; nn++)
                    mma_f16(s[np * 2 + nn], Ql, Kf + 2 * nn);
            }
        }

        float mx0 = -INFINITY, mx1 = -INFINITY;
#pragma unroll
        for (int i = 0; i < 8; i++) {
            mx0 = fmaxf(mx0, fmaxf(s[i][0], s[i][1]));
            mx1 = fmaxf(mx1, fmaxf(s[i][2], s[i][3]));
        }
        mx0 = fmaxf(mx0, __shfl_xor_sync(0xffffffffu, mx0, 1));
        mx0 = fmaxf(mx0, __shfl_xor_sync(0xffffffffu, mx0, 2));
        mx1 = fmaxf(mx1, __shfl_xor_sync(0xffffffffu, mx1, 1));
        mx1 = fmaxf(mx1, __shfl_xor_sync(0xffffffffu, mx1, 2));

        float mn0 = fmaxf(m0, mx0), mn1 = fmaxf(m1, mx1);
        float al0 = __expf(m0 - mn0), al1 = __expf(m1 - mn1);
        m0 = mn0; m1 = mn1;

        float rs0 = 0.f, rs1 = 0.f;
#pragma unroll
        for (int i = 0; i < 8; i++) {
            s[i][0] = __expf(s[i][0] - mn0);
            s[i][1] = __expf(s[i][1] - mn0);
            s[i][2] = __expf(s[i][2] - mn1);
            s[i][3] = __expf(s[i][3] - mn1);
            rs0 += s[i][0] + s[i][1];
            rs1 += s[i][2] + s[i][3];
        }
        rs0 += __shfl_xor_sync(0xffffffffu, rs0, 1);
        rs0 += __shfl_xor_sync(0xffffffffu, rs0, 2);
        rs1 += __shfl_xor_sync(0xffffffffu, rs1, 1);
        rs1 += __shfl_xor_sync(0xffffffffu, rs1, 2);
        l0 = l0 * al0 + rs0;
        l1 = l1 * al1 + rs1;
#pragma unroll
        for (int i = 0; i < 8; i++) {
            o[i][0] *= al0; o[i][1] *= al0;
            o[i][2] *= al1; o[i][3] *= al1;
        }

#pragma unroll
        for (int j = 0; j < 4; j++) {
            uint32_t Ph[4], Pl[4];
            pack_hl(s[2*j][0],   s[2*j][1],   Ph[0], Pl[0]);
            pack_hl(s[2*j][2],   s[2*j][3],   Ph[1], Pl[1]);
            pack_hl(s[2*j+1][0], s[2*j+1][1], Ph[2], Pl[2]);
            pack_hl(s[2*j+1][2], s[2*j+1][3], Ph[3], Pl[3]);
#pragma unroll
            for (int np = 0; np < 4; np++) {
                uint32_t rv = kb + AKBUF + (j * 16 + v_row) * ASTRIDE
                              + (np * 16 + v_c8) * 2;
                uint32_t Vf[4];
                ldsm4t(rv, Vf);
#pragma unroll
                for (int nn = 0; nn < 2; nn++)
                    mma_f16(o[np * 2 + nn], Ph, Vf + 2 * nn);
#pragma unroll
                for (int nn = 0; nn < 2; nn++)
                    mma_f16(o[np * 2 + nn], Pl, Vf + 2 * nn);
            }
        }
    }

    // epilogue: x single-rounded into g_x
    float inv0 = 1.0f / l0, inv1 = 1.0f / l1;
    const int b = bh >> 4;
    const int h = bh & (NHEAD - 1);
    const int qrow = q0 + wid * 16 + (lane >> 2);
#pragma unroll
    for (int nf = 0; nf < 8; nf++) {
        int d = h * DK + nf * 8 + (lane & 3) * 2;
        size_t idx0 = ((size_t)b * SEQ + qrow) * DMODEL + d;
        *(uint32_t*)&g_x[idx0] = pack_h(o[nf][0] * inv0, o[nf][1] * inv0);
        size_t idx1 = ((size_t)b * SEQ + qrow + 8) * DMODEL + d;
        *(uint32_t*)&g_x[idx1] = pack_h(o[nf][2] * inv1, o[nf][3] * inv1);
    }
}

// ---------------------------------------------------------------------------
extern "C" void kernel_launch(void* const* d_in, const int* in_sizes, int n_in,
                              void* d_out, int out_size)
{
    (void)in_sizes; (void)n_in; (void)out_size;
    const float* query = (const float*)d_in[0];
    const float* key   = (const float*)d_in[1];
    const float* value = (const float*)d_in[2];
    const float* Wq = (const float*)d_in[3];
    const float* bq = (const float*)d_in[4];
    const float* Wk = (const float*)d_in[5];
    const float* bk = (const float*)d_in[6];
    const float* Wv = (const float*)d_in[7];
    const float* bv = (const float*)d_in[8];
    const float* Wo = (const float*)d_in[9];
    const float* bo = (const float*)d_in[10];
    float* out = (float*)d_out;

    cudaFuncSetAttribute(gemm_mma_kernel<0>, cudaFuncAttributeMaxDynamicSharedMemorySize,
                         GEMM_SMEM);
    cudaFuncSetAttribute(gemm_mma_kernel<1>, cudaFuncAttributeMaxDynamicSharedMemorySize,
                         GEMM_SMEM);
    cudaFuncSetAttribute(attn_mma_kernel, cudaFuncAttributeMaxDynamicSharedMemorySize,
                         ATT_SMEM);

    const int nA4 = (int)(ACTN / 4);
    const int nW4 = (int)(WN / 4);

    cvt_all_kernel<<<dim3(nA4 / 256, 7), 256>>>(query, key, value, Wq, Wk, Wv, Wo,
                                                nA4, nW4);

    gemm_mma_kernel<0><<<dim3(8, 64, 3), 256, GEMM_SMEM>>>(bq, bk, bv, nullptr);

    attn_mma_kernel<<<dim3(SEQ / 128, BATCH * NHEAD), 256, ATT_SMEM>>>();

    gemm_mma_kernel<1><<<dim3(8, 64, 1), 256, GEMM_SMEM>>>(bo, bo, bo, out);
}

// round 16
// speedup vs baseline: 2.0347x; 1.2487x over previous
#include <cuda_runtime.h>
#include <cuda_fp16.h>
#include <math.h>
#include <stdint.h>

#define NHEAD 16
#define DK 64
#define DMODEL 1024
#define BATCH 4
#define SEQ 2048
#define MTOT (BATCH*SEQ)                  // 8192
#define ACTN ((size_t)MTOT*DMODEL)
#define WN   ((size_t)DMODEL*DMODEL)
#define HS   ((size_t)BATCH*NHEAD*SEQ*DK)

// everything single-rounded fp16 now
__device__ __half g_a [3*ACTN];           // input acts q,k,v
__device__ __half g_x [ACTN];             // attn output
__device__ __half g_w [4*WN];
__device__ __half g_q [HS];               // Q (scaled by 1/8)
__device__ __half g_k [HS];
__device__ __half g_v [HS];

// ---------------- helpers ----------------
__device__ __forceinline__ uint32_t smem_u32(const void* p) {
    uint32_t a;
    asm("{ .reg .u64 t; cvta.to.shared.u64 t, %1; cvt.u32.u64 %0, t; }" : "=r"(a) : "l"(p));
    return a;
}
__device__ __forceinline__ void cp_async16(uint32_t dst, const void* src) {
    asm volatile("cp.async.cg.shared.global [%0], [%1], 16;" :: "r"(dst), "l"(src));
}
#define CP_COMMIT() asm volatile("cp.async.commit_group;" ::: "memory")
#define CP_WAIT(n)  asm volatile("cp.async.wait_group %0;" :: "n"(n) : "memory")

__device__ __forceinline__ void ldsm4(uint32_t a, uint32_t* r) {
    asm volatile("ldmatrix.sync.aligned.m8n8.x4.shared.b16 {%0,%1,%2,%3}, [%4];"
        : "=r"(r[0]), "=r"(r[1]), "=r"(r[2]), "=r"(r[3]) : "r"(a));
}
__device__ __forceinline__ void ldsm4t(uint32_t a, uint32_t* r) {
    asm volatile("ldmatrix.sync.aligned.m8n8.x4.trans.shared.b16 {%0,%1,%2,%3}, [%4];"
        : "=r"(r[0]), "=r"(r[1]), "=r"(r[2]), "=r"(r[3]) : "r"(a));
}
__device__ __forceinline__ void mma_f16(float* c, const uint32_t* a, const uint32_t* b) {
    asm volatile("mma.sync.aligned.m16n8k16.row.col.f32.f16.f16.f32 "
        "{%0,%1,%2,%3}, {%4,%5,%6,%7}, {%8,%9}, {%0,%1,%2,%3};"
        : "+f"(c[0]), "+f"(c[1]), "+f"(c[2]), "+f"(c[3])
        : "r"(a[0]), "r"(a[1]), "r"(a[2]), "r"(a[3]), "r"(b[0]), "r"(b[1]));
}
__device__ __forceinline__ uint32_t pack_h(float p0, float p1) {
    __half2 hv = __floats2half2_rn(p0, p1);
    return *(uint32_t*)&hv;
}

// ---------------------------------------------------------------------------
// fp32 -> fp16 single-round convert, acts + weights in ONE launch.
// ---------------------------------------------------------------------------
__global__ void cvt_all_kernel(const float* __restrict__ q, const float* __restrict__ k,
                               const float* __restrict__ v,
                               const float* __restrict__ w0, const float* __restrict__ w1,
                               const float* __restrict__ w2, const float* __restrict__ w3,
                               int nA4, int nW4)
{
    int z = blockIdx.y;
    int i = blockIdx.x * blockDim.x + threadIdx.x;
    const float* src;
    __half* dst;
    if (z < 3) {
        if (i >= nA4) return;
        src = (z == 0) ? q : (z == 1) ? k : v;
        dst = g_a + (size_t)z * ACTN;
    } else {
        if (i >= nW4) return;
        int w = z - 3;
        src = (w == 0) ? w0 : (w == 1) ? w1 : (w == 2) ? w2 : w3;
        dst = g_w + (size_t)w * WN;
    }
    float4 vv = ((const float4*)src)[i];
    ((uint32_t*)dst)[2*i]   = pack_h(vv.x, vv.y);
    ((uint32_t*)dst)[2*i+1] = pack_h(vv.z, vv.w);
}

// ---------------------------------------------------------------------------
// GEMM: 1-term fp16, 4-stage pipeline (pf=3).
// MODE 0: QKV fused (z selects slot; z==0 scaled by 1/8). MODE 1: final, fp32 out.
// CTA 128x128, K-chunk 32, 2 CTAs/SM. 8 warps 4(M)x2(N), warp 32x64.
// ---------------------------------------------------------------------------
#define GKC 32
#define GSTRIDE 80
#define GA_BUF (128*GSTRIDE)             // 10240
#define GSTAGE (2*GA_BUF)                // A, W = 20480
#define GNSTG 4
#define GEMM_SMEM (GNSTG*GSTAGE)         // 81920
#define GPF 3

__device__ __forceinline__ void g_load_stage(uint32_t base,
                                             const __half* A_g, const __half* W_g,
                                             int bm, int bn, int k0, int tid)
{
#pragma unroll
    for (int j = 0; j < 4; j++) {
        int g = tid + 256 * j;
        int buf = g >> 9;                 // 0:A 1:W
        int cid = g & 511;
        int row = cid >> 2;
        int ch  = cid & 3;
        const __half* src = buf ? W_g : A_g;
        int rbase = buf ? bn : bm;
        cp_async16(base + buf * GA_BUF + row * GSTRIDE + ch * 16,
                   src + (size_t)(rbase + row) * DMODEL + k0 + ch * 8);
    }
}

template<int MODE>
__global__ __launch_bounds__(256, 2)
void gemm_mma_kernel(const float* __restrict__ b0, const float* __restrict__ b1,
                     const float* __restrict__ b2, float* __restrict__ Cout)
{
    extern __shared__ __align__(128) char smg[];
    const uint32_t sb = smem_u32(smg);
    const int tid = threadIdx.x;
    const int lane = tid & 31;
    const int wid = tid >> 5;
    const int wr = (wid >> 1) * 32;
    const int wn = (wid & 1) * 64;
    const int bm = blockIdx.y * 128;
    const int bn = blockIdx.x * 128;
    const int z = blockIdx.z;

    const __half* A_g = (MODE == 0) ? g_a + (size_t)z * ACTN : g_x;
    const __half* W_g = g_w + (size_t)((MODE == 0) ? z : 3) * WN;
    const float* bias = (MODE == 1) ? b0 : (z == 0) ? b0 : (z == 1) ? b1 : b2;

    float acc[2][8][4];
#pragma unroll
    for (int a = 0; a < 2; a++)
#pragma unroll
        for (int b = 0; b < 8; b++)
#pragma unroll
            for (int c = 0; c < 4; c++) acc[a][b][c] = 0.f;

#pragma unroll
    for (int p = 0; p < GPF; p++) {
        g_load_stage(sb + p * GSTAGE, A_g, W_g, bm, bn, p * GKC, tid);
        CP_COMMIT();
    }

    const int NIT = DMODEL / GKC;   // 32
    const uint32_t a_row = (lane & 15);
    const uint32_t a_k8  = (lane >> 4) << 3;
    const uint32_t b_row = ((lane >> 4) << 3) + (lane & 7);
    const uint32_t b_k8  = ((lane >> 3) & 1) << 3;

    for (int it = 0; it < NIT; it++) {
        int rem = NIT - 1 - it;
        int pend = (rem < GPF - 1) ? rem : (GPF - 1);
        if      (pend >= 2) { CP_WAIT(2); }
        else if (pend == 1) { CP_WAIT(1); }
        else                { CP_WAIT(0); }
        __syncthreads();

        if (it + GPF < NIT) {
            g_load_stage(sb + ((it + GPF) % GNSTG) * GSTAGE, A_g, W_g,
                         bm, bn, (it + GPF) * GKC, tid);
            CP_COMMIT();
        }

        uint32_t base = sb + (it % GNSTG) * GSTAGE;
#pragma unroll
        for (int ks = 0; ks < 2; ks++) {
            const int k0 = ks * 16;
            uint32_t Af[2][4], Bf[4][4];
#pragma unroll
            for (int mf = 0; mf < 2; mf++) {
                uint32_t ra = base + (wr + mf * 16 + a_row) * GSTRIDE + (k0 + a_k8) * 2;
                ldsm4(ra, Af[mf]);
            }
#pragma unroll
            for (int np = 0; np < 4; np++) {
                uint32_t rb = base + GA_BUF + (wn + np * 16 + b_row) * GSTRIDE
                              + (k0 + b_k8) * 2;
                ldsm4(rb, Bf[np]);
            }
#pragma unroll
            for (int np = 0; np < 4; np++)
#pragma unroll
                for (int nn = 0; nn < 2; nn++)
#pragma unroll
                    for (int mf = 0; mf < 2; mf++)
                        mma_f16(acc[mf][np * 2 + nn], Af[mf], Bf[np] + 2 * nn);
        }
    }

    // epilogue
    const float sc = (MODE == 0 && z == 0) ? 0.125f : 1.0f;
    __half* dst = (z == 0) ? g_q : (z == 1) ? g_k : g_v;
#pragma unroll
    for (int mf = 0; mf < 2; mf++) {
#pragma unroll
        for (int nf = 0; nf < 8; nf++) {
            int r0 = bm + wr + mf * 16 + (lane >> 2);
            int c0 = bn + wn + nf * 8 + (lane & 3) * 2;
            float bs0 = bias[c0], bs1 = bias[c0 + 1];
#pragma unroll
            for (int hh = 0; hh < 2; hh++) {
                int row = r0 + 8 * hh;
                float v0 = (acc[mf][nf][2 * hh + 0] + bs0) * sc;
                float v1 = (acc[mf][nf][2 * hh + 1] + bs1) * sc;
                if (MODE == 0) {
                    int hd = c0 >> 6, d = c0 & 63;
                    int b = row >> 11, s = row & (SEQ - 1);
                    size_t idx = ((((size_t)b * NHEAD + hd) * SEQ) + s) * DK + d;
                    *(uint32_t*)&dst[idx] = pack_h(v0, v1);
                } else {
                    float2 o = make_float2(v0, v1);
                    *(float2*)&Cout[(size_t)row * DMODEL + c0] = o;
                }
            }
        }
    }
}

// ---------------------------------------------------------------------------
// Flash attention, pure 1-term fp16: S = Q K^T (Q persistent in regs, scaled),
// O = P V (P single-rounded). 4-stage KV ring, 2 CTAs/SM.
// ---------------------------------------------------------------------------
#define ASTRIDE 144
#define AQBUF (128*ASTRIDE)          // 18432
#define AKBUF (64*ASTRIDE)           // 9216
#define ASTAGE (2*AKBUF)             // K, V = 18432
#define ANSTG 4
#define APF 3
#define ATT_SMEM (AQBUF + ANSTG*ASTAGE)   // 92160

__device__ __forceinline__ void a_load_kv(uint32_t sb, int stg, int bh, int kt, int tid)
{
    uint32_t base = sb + AQBUF + stg * ASTAGE;
#pragma unroll
    for (int j = 0; j < 4; j++) {
        int g = tid + 256 * j;
        int buf = g >> 9;             // 0:K 1:V
        int cid = g & 511;
        int row = cid >> 3;
        int ch  = cid & 7;
        const __half* src = buf ? g_v : g_k;
        const void* gp = src + ((size_t)bh * SEQ + kt * 64 + row) * DK + ch * 8;
        cp_async16(base + buf * AKBUF + row * ASTRIDE + ch * 16, gp);
    }
}

__global__ __launch_bounds__(256, 2)
void attn_mma_kernel()
{
    extern __shared__ __align__(128) char sma[];
    const uint32_t sb = smem_u32(sma);
    const int tid = threadIdx.x;
    const int lane = tid & 31;
    const int wid = tid >> 5;
    const int bh = blockIdx.y;
    const int q0 = blockIdx.x * 128;

    // Q tile (single) via cp.async
#pragma unroll
    for (int j = 0; j < 4; j++) {
        int g = tid + 256 * j;        // 0..1023
        int row = g >> 3;
        int ch  = g & 7;
        const void* gp = g_q + ((size_t)bh * SEQ + q0 + row) * DK + ch * 8;
        cp_async16(sb + row * ASTRIDE + ch * 16, gp);
    }
    CP_COMMIT();
    a_load_kv(sb, 0, bh, 0, tid); CP_COMMIT();
    a_load_kv(sb, 1, bh, 1, tid); CP_COMMIT();
    a_load_kv(sb, 2, bh, 2, tid); CP_COMMIT();

    const uint32_t a_row = (lane & 15);
    const uint32_t a_k8  = (lane >> 4) << 3;
    const uint32_t b_row = ((lane >> 4) << 3) + (lane & 7);
    const uint32_t b_k8  = ((lane >> 3) & 1) << 3;
    const uint32_t v_row = (((lane >> 3) & 1) << 3) + (lane & 7);
    const uint32_t v_c8  = (lane >> 4) << 3;
    const int wq = wid * 16;

    uint32_t Qf[4][4];               // persistent Q fragments (16 regs)
    float o[8][4];
#pragma unroll
    for (int i = 0; i < 8; i++)
#pragma unroll
        for (int k = 0; k < 4; k++) o[i][k] = 0.f;
    float m0 = -INFINITY, m1 = -INFINITY, l0 = 0.f, l1 = 0.f;

    const int NT = SEQ / 64;   // 32
    for (int it = 0; it < NT; it++) {
        int rem = NT - 1 - it;
        int pend = (rem < APF - 1) ? rem : (APF - 1);
        if      (pend >= 2) { CP_WAIT(2); }
        else if (pend == 1) { CP_WAIT(1); }
        else                { CP_WAIT(0); }
        __syncthreads();

        if (it == 0) {
            // Q resident now (wait left <=2 KV groups pending; Q group drained)
#pragma unroll
            for (int ks = 0; ks < 4; ks++) {
                uint32_t ra = sb + (wq + a_row) * ASTRIDE + (ks * 16 + a_k8) * 2;
                ldsm4(ra, Qf[ks]);
            }
        }

        if (it + APF < NT) {
            a_load_kv(sb, (it + APF) % ANSTG, bh, it + APF, tid);
            CP_COMMIT();
        }

        uint32_t kb = sb + AQBUF + (it % ANSTG) * ASTAGE;

        // ---- S = Q K^T (Q carries 1/8) ----
        float s[8][4];
#pragma unroll
        for (int i = 0; i < 8; i++)
#pragma unroll
            for (int k = 0; k < 4; k++) s[i][k] = 0.f;

#pragma unroll
        for (int ks = 0; ks < 4; ks++) {
#pragma unroll
            for (int np = 0; np < 4; np++) {
                uint32_t rb = kb + (np * 16 + b_row) * ASTRIDE + (ks * 16 + b_k8) * 2;
                uint32_t Kf[4];
                ldsm4(rb, Kf);
                mma_f16(s[np * 2 + 0], Qf[ks], Kf);
                mma_f16(s[np * 2 + 1], Qf[ks], Kf + 2);
            }
        }

        // ---- online softmax ----
        float mx0 = -INFINITY, mx1 = -INFINITY;
#pragma unroll
        for (int i = 0; i < 8; i++) {
            mx0 = fmaxf(mx0, fmaxf(s[i][0], s[i][1]));
            mx1 = fmaxf(mx1, fmaxf(s[i][2], s[i][3]));
        }
        mx0 = fmaxf(mx0, __shfl_xor_sync(0xffffffffu, mx0, 1));
        mx0 = fmaxf(mx0, __shfl_xor_sync(0xffffffffu, mx0, 2));
        mx1 = fmaxf(mx1, __shfl_xor_sync(0xffffffffu, mx1, 1));
        mx1 = fmaxf(mx1, __shfl_xor_sync(0xffffffffu, mx1, 2));

        float mn0 = fmaxf(m0, mx0), mn1 = fmaxf(m1, mx1);
        float al0 = __expf(m0 - mn0), al1 = __expf(m1 - mn1);
        m0 = mn0; m1 = mn1;

        float rs0 = 0.f, rs1 = 0.f;
#pragma unroll
        for (int i = 0; i < 8; i++) {
            s[i][0] = __expf(s[i][0] - mn0);
            s[i][1] = __expf(s[i][1] - mn0);
            s[i][2] = __expf(s[i][2] - mn1);
            s[i][3] = __expf(s[i][3] - mn1);
            rs0 += s[i][0] + s[i][1];
            rs1 += s[i][2] + s[i][3];
        }
        rs0 += __shfl_xor_sync(0xffffffffu, rs0, 1);
        rs0 += __shfl_xor_sync(0xffffffffu, rs0, 2);
        rs1 += __shfl_xor_sync(0xffffffffu, rs1, 1);
        rs1 += __shfl_xor_sync(0xffffffffu, rs1, 2);
        l0 = l0 * al0 + rs0;
        l1 = l1 * al1 + rs1;
#pragma unroll
        for (int i = 0; i < 8; i++) {
            o[i][0] *= al0; o[i][1] *= al0;
            o[i][2] *= al1; o[i][3] *= al1;
        }

        // ---- O += P V (P single-rounded) ----
#pragma unroll
        for (int j = 0; j < 4; j++) {
            uint32_t Pf[4];
            Pf[0] = pack_h(s[2*j][0],   s[2*j][1]);
            Pf[1] = pack_h(s[2*j][2],   s[2*j][3]);
            Pf[2] = pack_h(s[2*j+1][0], s[2*j+1][1]);
            Pf[3] = pack_h(s[2*j+1][2], s[2*j+1][3]);
#pragma unroll
            for (int np = 0; np < 4; np++) {
                uint32_t rv = kb + AKBUF + (j * 16 + v_row) * ASTRIDE
                              + (np * 16 + v_c8) * 2;
                uint32_t Vf[4];
                ldsm4t(rv, Vf);
                mma_f16(o[np * 2 + 0], Pf, Vf);
                mma_f16(o[np * 2 + 1], Pf, Vf + 2);
            }
        }
    }

    // epilogue: x single-rounded into g_x
    float inv0 = 1.0f / l0, inv1 = 1.0f / l1;
    const int b = bh >> 4;
    const int h = bh & (NHEAD - 1);
    const int qrow = q0 + wid * 16 + (lane >> 2);
#pragma unroll
    for (int nf = 0; nf < 8; nf++) {
        int d = h * DK + nf * 8 + (lane & 3) * 2;
        size_t idx0 = ((size_t)b * SEQ + qrow) * DMODEL + d;
        *(uint32_t*)&g_x[idx0] = pack_h(o[nf][0] * inv0, o[nf][1] * inv0);
        size_t idx1 = ((size_t)b * SEQ + qrow + 8) * DMODEL + d;
        *(uint32_t*)&g_x[idx1] = pack_h(o[nf][2] * inv1, o[nf][3] * inv1);
    }
}

// ---------------------------------------------------------------------------
extern "C" void kernel_launch(void* const* d_in, const int* in_sizes, int n_in,
                              void* d_out, int out_size)
{
    (void)in_sizes; (void)n_in; (void)out_size;
    const float* query = (const float*)d_in[0];
    const float* key   = (const float*)d_in[1];
    const float* value = (const float*)d_in[2];
    const float* Wq = (const float*)d_in[3];
    const float* bq = (const float*)d_in[4];
    const float* Wk = (const float*)d_in[5];
    const float* bk = (const float*)d_in[6];
    const float* Wv = (const float*)d_in[7];
    const float* bv = (const float*)d_in[8];
    const float* Wo = (const float*)d_in[9];
    const float* bo = (const float*)d_in[10];
    float* out = (float*)d_out;

    cudaFuncSetAttribute(gemm_mma_kernel<0>, cudaFuncAttributeMaxDynamicSharedMemorySize,
                         GEMM_SMEM);
    cudaFuncSetAttribute(gemm_mma_kernel<1>, cudaFuncAttributeMaxDynamicSharedMemorySize,
                         GEMM_SMEM);
    cudaFuncSetAttribute(attn_mma_kernel, cudaFuncAttributeMaxDynamicSharedMemorySize,
                         ATT_SMEM);

    const int nA4 = (int)(ACTN / 4);
    const int nW4 = (int)(WN / 4);

    cvt_all_kernel<<<dim3(nA4 / 256, 7), 256>>>(query, key, value, Wq, Wk, Wv, Wo,
                                                nA4, nW4);

    gemm_mma_kernel<0><<<dim3(8, 64, 3), 256, GEMM_SMEM>>>(bq, bk, bv, nullptr);

    attn_mma_kernel<<<dim3(SEQ / 128, BATCH * NHEAD), 256, ATT_SMEM>>>();

    gemm_mma_kernel<1><<<dim3(8, 64, 1), 256, GEMM_SMEM>>>(bo, bo, bo, out);
}